// round 16
// baseline (speedup 1.0000x reference)
#include <cuda_runtime.h>
#include <cstdint>

// Elman RNN split:
//   A) u[n,t,:] = x[n,t,:] @ W_ih^T + b_ih + b_hh   (parallel, MLP-2 streaming)
//   B) h_{t+1}  = tanh(u_t + h_t @ W_hh^T)          (serial, warp-INDEPENDENT)
// N=2048, T=512, I=32, H=64, O=1.
// B: 1024 blocks x 64 thr; warp w owns sample 2*bid+w alone. Lane l owns units
//    (2l,2l+1), W_hh rows in 128 regs, per-warp smem h ping-pong, __syncwarp
//    only (no block barriers -> decorrelated warps). <=146 regs -> 7 blocks/SM
//    -> single wave @ 3.5 warps/SMSP.

#define TT 512
#define NN 2048

typedef unsigned long long ull;

__device__ float g_u[(size_t)NN * TT * 64];   // 268 MB scratch

__device__ __forceinline__ float tanh_acc(float s) {
    float e = __expf(2.0f * s);
    return 1.0f - __fdividef(2.0f, e + 1.0f);
}

// ---------------- Kernel A: streaming precompute of u, distance-2 prefetch ----------------
// grid = 2048 (block = sample), block = 128 = 4 warps. Warp w covers rows
// [128w,128w+128) in 4-row groups; 2 group-LDGs in flight per warp.
__global__ void __launch_bounds__(128) precompute_u_kernel(
    const float* __restrict__ x,      // [N, T, I]
    const float* __restrict__ W_ih,   // [H, I]
    const float* __restrict__ b_ih,   // [H]
    const float* __restrict__ b_hh)   // [H]
{
    __shared__ __align__(16) float xs[4][2][128];   // [warp][parity][4 rows x 32]

    const int w  = threadIdx.x >> 5;
    const int l  = threadIdx.x & 31;
    const int n  = blockIdx.x;
    const int u0 = 2 * l;
    const int u1 = u0 + 1;

    ull W0[16], W1[16];
    {
        const ull* q0 = reinterpret_cast<const ull*>(W_ih + u0 * 32);
        const ull* q1 = reinterpret_cast<const ull*>(W_ih + u1 * 32);
        #pragma unroll
        for (int k = 0; k < 16; k++) { W0[k] = __ldg(q0 + k); W1[k] = __ldg(q1 + k); }
    }
    const float bias0 = __ldg(b_ih + u0) + __ldg(b_hh + u0);
    const float bias1 = __ldg(b_ih + u1) + __ldg(b_hh + u1);

    const int t0 = w * 128;
    const float* xb = x + (size_t)n * TT * 32;
    float* ub = g_u + (size_t)n * TT * 64;

    // prime: group 0 in smem, group 1 in registers (vn), group 2 LDG issued (vn2)
    {
        const float4 v0 = __ldg(reinterpret_cast<const float4*>(xb + t0 * 32) + l);
        reinterpret_cast<float4*>(&xs[w][0][0])[l] = v0;
    }
    float4 vn  = __ldg(reinterpret_cast<const float4*>(xb + (t0 + 4) * 32) + l);
    float4 vn2 = __ldg(reinterpret_cast<const float4*>(xb + (t0 + 8) * 32) + l);
    __syncwarp();

    int p = 0;
    for (int g = 0; g < 32; g++) {
        // compute 4 rows of group g from smem parity p
        #pragma unroll
        for (int r = 0; r < 4; r++) {
            const ulonglong2* vp =
                reinterpret_cast<const ulonglong2*>(&xs[w][p][r * 32]);
            ull a0 = 0ull, a1 = 0ull;
            #pragma unroll
            for (int q = 0; q < 8; q++) {
                const ulonglong2 v = vp[q];
                asm("fma.rn.f32x2 %0, %1, %2, %0;" : "+l"(a0) : "l"(v.x), "l"(W0[2 * q]));
                asm("fma.rn.f32x2 %0, %1, %2, %0;" : "+l"(a1) : "l"(v.x), "l"(W1[2 * q]));
                asm("fma.rn.f32x2 %0, %1, %2, %0;" : "+l"(a0) : "l"(v.y), "l"(W0[2 * q + 1]));
                asm("fma.rn.f32x2 %0, %1, %2, %0;" : "+l"(a1) : "l"(v.y), "l"(W1[2 * q + 1]));
            }
            float r0x, r0y, r1x, r1y;
            asm("mov.b64 {%0, %1}, %2;" : "=f"(r0x), "=f"(r0y) : "l"(a0));
            asm("mov.b64 {%0, %1}, %2;" : "=f"(r1x), "=f"(r1y) : "l"(a1));
            const int t = t0 + 4 * g + r;
            *reinterpret_cast<float2*>(ub + t * 64 + u0) =
                make_float2(bias0 + r0x + r0y, bias1 + r1x + r1y);
        }

        // stage group g+1 from registers; issue LDG for group g+3
        reinterpret_cast<float4*>(&xs[w][p ^ 1][0])[l] = vn;
        vn = vn2;
        vn2 = (g + 3 < 32)
            ? __ldg(reinterpret_cast<const float4*>(xb + (t0 + 4 * (g + 3)) * 32) + l)
            : make_float4(0.f, 0.f, 0.f, 0.f);
        __syncwarp();
        p ^= 1;
    }
}

// ---------------- Kernel B: serial recurrence, warp-independent ----------------
__global__ void __launch_bounds__(64, 7) rnn_rec_kernel(
    const float* __restrict__ W_hh,   // [H, H]
    const float* __restrict__ fc_w,   // [1, H]
    const float* __restrict__ fc_b,   // [1]
    float* __restrict__ out)          // [N, 1]
{
    __shared__ __align__(16) float hb[2][2][64];   // [warp][parity][unit] - per-warp private

    const int w  = threadIdx.x >> 5;   // warp = independent sample
    const int l  = threadIdx.x & 31;
    const int n  = 2 * blockIdx.x + w;
    const int u0 = 2 * l;
    const int u1 = u0 + 1;

    // W_hh rows for this lane's 2 units: 64 ull = 128 regs
    ull W0[32], W1[32];
    {
        const ull* p0 = reinterpret_cast<const ull*>(W_hh + u0 * 64);
        const ull* p1 = reinterpret_cast<const ull*>(W_hh + u1 * 64);
        #pragma unroll
        for (int k = 0; k < 32; k++) { W0[k] = __ldg(p0 + k); W1[k] = __ldg(p1 + k); }
    }

    // u stream: lane l reads float2 (units u0,u1); 256B coalesced per warp-step
    const float2* up = reinterpret_cast<const float2*>(g_u + (size_t)n * TT * 64) + l;

    // init h0 = ones; prefetch u_0, u_1
    *reinterpret_cast<float2*>(&hb[w][0][u0]) = make_float2(1.0f, 1.0f);
    float2 uc = __ldg(up);
    float2 un = __ldg(up + 32);
    __syncwarp();

    float h0 = 1.0f, h1 = 1.0f;

    for (int t = 0; t < TT; t++) {
        const int cur = t & 1;

        // distance-2 u prefetch (DRAM latency < 2 step-walls)
        const float2 u2 = (t + 2 < TT) ? __ldg(up + (t + 2) * 32)
                                       : make_float2(0.0f, 0.0f);

        const ulonglong2* vp = reinterpret_cast<const ulonglong2*>(&hb[w][cur][0]);

        // 2 chains (one per unit); u_t seeds the lo halves; spacing 4cy per chain
        float2 s0 = make_float2(uc.x, 0.0f);
        float2 s1 = make_float2(uc.y, 0.0f);
        ull a0 = *reinterpret_cast<ull*>(&s0);
        ull a1 = *reinterpret_cast<ull*>(&s1);

        #pragma unroll
        for (int g = 0; g < 16; g++) {
            const ulonglong2 v = vp[g];
            asm("fma.rn.f32x2 %0, %1, %2, %0;" : "+l"(a0) : "l"(v.x), "l"(W0[2 * g]));
            asm("fma.rn.f32x2 %0, %1, %2, %0;" : "+l"(a1) : "l"(v.x), "l"(W1[2 * g]));
            asm("fma.rn.f32x2 %0, %1, %2, %0;" : "+l"(a0) : "l"(v.y), "l"(W0[2 * g + 1]));
            asm("fma.rn.f32x2 %0, %1, %2, %0;" : "+l"(a1) : "l"(v.y), "l"(W1[2 * g + 1]));
        }

        float r0x, r0y, r1x, r1y;
        asm("mov.b64 {%0, %1}, %2;" : "=f"(r0x), "=f"(r0y) : "l"(a0));
        asm("mov.b64 {%0, %1}, %2;" : "=f"(r1x), "=f"(r1y) : "l"(a1));

        h0 = tanh_acc(r0x + r0y);
        h1 = tanh_acc(r1x + r1y);

        // publish into the other parity of this warp's private buffer
        *reinterpret_cast<float2*>(&hb[w][cur ^ 1][u0]) = make_float2(h0, h1);
        __syncwarp();

        uc = un; un = u2;
    }

    // ---- output head: sigmoid(h . fc_w + fc_b), pure warp reduction ----
    float p = h0 * fc_w[u0] + h1 * fc_w[u1];
    #pragma unroll
    for (int o = 16; o; o >>= 1) p += __shfl_xor_sync(0xffffffffu, p, o);
    if (l == 0)
        out[n] = __fdividef(1.0f, 1.0f + __expf(-(p + fc_b[0])));
}

extern "C" void kernel_launch(void* const* d_in, const int* in_sizes, int n_in,
                              void* d_out, int out_size) {
    const float* x    = (const float*)d_in[0];
    const float* W_ih = (const float*)d_in[1];
    const float* W_hh = (const float*)d_in[2];
    const float* b_ih = (const float*)d_in[3];
    const float* b_hh = (const float*)d_in[4];
    const float* fc_w = (const float*)d_in[5];
    const float* fc_b = (const float*)d_in[6];
    float* out = (float*)d_out;

    precompute_u_kernel<<<NN, 128>>>(x, W_ih, b_ih, b_hh);
    rnn_rec_kernel<<<NN / 2, 64>>>(W_hh, fc_w, fc_b, out);
}

// round 17
// speedup vs baseline: 1.0059x; 1.0059x over previous
#include <cuda_runtime.h>
#include <cstdint>

// Elman RNN split:
//   A) u[n,t,:] = x[n,t,:] @ W_ih^T + b_ih + b_hh   (parallel, MLP-2 streaming)
//   B) h_{t+1}  = tanh(u_t + h_t @ W_hh^T)          (serial, warp-INDEPENDENT)
// N=2048, T=512, I=32, H=64, O=1.
// B: 1024 blocks x 64 thr; warp w owns sample 2*bid+w alone. Lane l owns units
//    (2l,2l+1), W_hh rows in 128 regs, per-warp smem h ping-pong, __syncwarp
//    only (no block barriers -> decorrelated warps). <=146 regs -> 7 blocks/SM
//    -> single wave @ 3.5 warps/SMSP.

#define TT 512
#define NN 2048

typedef unsigned long long ull;

__device__ float g_u[(size_t)NN * TT * 64];   // 268 MB scratch

__device__ __forceinline__ float tanh_acc(float s) {
    float e = __expf(2.0f * s);
    return 1.0f - __fdividef(2.0f, e + 1.0f);
}

// ---------------- Kernel A: streaming precompute of u, distance-2 prefetch ----------------
// grid = 2048 (block = sample), block = 128 = 4 warps. Warp w covers rows
// [128w,128w+128) in 4-row groups; 2 group-LDGs in flight per warp.
__global__ void __launch_bounds__(128) precompute_u_kernel(
    const float* __restrict__ x,      // [N, T, I]
    const float* __restrict__ W_ih,   // [H, I]
    const float* __restrict__ b_ih,   // [H]
    const float* __restrict__ b_hh)   // [H]
{
    __shared__ __align__(16) float xs[4][2][128];   // [warp][parity][4 rows x 32]

    const int w  = threadIdx.x >> 5;
    const int l  = threadIdx.x & 31;
    const int n  = blockIdx.x;
    const int u0 = 2 * l;
    const int u1 = u0 + 1;

    ull W0[16], W1[16];
    {
        const ull* q0 = reinterpret_cast<const ull*>(W_ih + u0 * 32);
        const ull* q1 = reinterpret_cast<const ull*>(W_ih + u1 * 32);
        #pragma unroll
        for (int k = 0; k < 16; k++) { W0[k] = __ldg(q0 + k); W1[k] = __ldg(q1 + k); }
    }
    const float bias0 = __ldg(b_ih + u0) + __ldg(b_hh + u0);
    const float bias1 = __ldg(b_ih + u1) + __ldg(b_hh + u1);

    const int t0 = w * 128;
    const float* xb = x + (size_t)n * TT * 32;
    float* ub = g_u + (size_t)n * TT * 64;

    // prime: group 0 in smem, group 1 in registers (vn), group 2 LDG issued (vn2)
    {
        const float4 v0 = __ldg(reinterpret_cast<const float4*>(xb + t0 * 32) + l);
        reinterpret_cast<float4*>(&xs[w][0][0])[l] = v0;
    }
    float4 vn  = __ldg(reinterpret_cast<const float4*>(xb + (t0 + 4) * 32) + l);
    float4 vn2 = __ldg(reinterpret_cast<const float4*>(xb + (t0 + 8) * 32) + l);
    __syncwarp();

    int p = 0;
    for (int g = 0; g < 32; g++) {
        // compute 4 rows of group g from smem parity p
        #pragma unroll
        for (int r = 0; r < 4; r++) {
            const ulonglong2* vp =
                reinterpret_cast<const ulonglong2*>(&xs[w][p][r * 32]);
            ull a0 = 0ull, a1 = 0ull;
            #pragma unroll
            for (int q = 0; q < 8; q++) {
                const ulonglong2 v = vp[q];
                asm("fma.rn.f32x2 %0, %1, %2, %0;" : "+l"(a0) : "l"(v.x), "l"(W0[2 * q]));
                asm("fma.rn.f32x2 %0, %1, %2, %0;" : "+l"(a1) : "l"(v.x), "l"(W1[2 * q]));
                asm("fma.rn.f32x2 %0, %1, %2, %0;" : "+l"(a0) : "l"(v.y), "l"(W0[2 * q + 1]));
                asm("fma.rn.f32x2 %0, %1, %2, %0;" : "+l"(a1) : "l"(v.y), "l"(W1[2 * q + 1]));
            }
            float r0x, r0y, r1x, r1y;
            asm("mov.b64 {%0, %1}, %2;" : "=f"(r0x), "=f"(r0y) : "l"(a0));
            asm("mov.b64 {%0, %1}, %2;" : "=f"(r1x), "=f"(r1y) : "l"(a1));
            const int t = t0 + 4 * g + r;
            *reinterpret_cast<float2*>(ub + t * 64 + u0) =
                make_float2(bias0 + r0x + r0y, bias1 + r1x + r1y);
        }

        // stage group g+1 from registers; issue LDG for group g+3
        reinterpret_cast<float4*>(&xs[w][p ^ 1][0])[l] = vn;
        vn = vn2;
        vn2 = (g + 3 < 32)
            ? __ldg(reinterpret_cast<const float4*>(xb + (t0 + 4 * (g + 3)) * 32) + l)
            : make_float4(0.f, 0.f, 0.f, 0.f);
        __syncwarp();
        p ^= 1;
    }
}

// ---------------- Kernel B: serial recurrence, warp-independent ----------------
__global__ void __launch_bounds__(64, 7) rnn_rec_kernel(
    const float* __restrict__ W_hh,   // [H, H]
    const float* __restrict__ fc_w,   // [1, H]
    const float* __restrict__ fc_b,   // [1]
    float* __restrict__ out)          // [N, 1]
{
    __shared__ __align__(16) float hb[2][2][64];   // [warp][parity][unit] - per-warp private

    const int w  = threadIdx.x >> 5;   // warp = independent sample
    const int l  = threadIdx.x & 31;
    const int n  = 2 * blockIdx.x + w;
    const int u0 = 2 * l;
    const int u1 = u0 + 1;

    // W_hh rows for this lane's 2 units: 64 ull = 128 regs
    ull W0[32], W1[32];
    {
        const ull* p0 = reinterpret_cast<const ull*>(W_hh + u0 * 64);
        const ull* p1 = reinterpret_cast<const ull*>(W_hh + u1 * 64);
        #pragma unroll
        for (int k = 0; k < 32; k++) { W0[k] = __ldg(p0 + k); W1[k] = __ldg(p1 + k); }
    }

    // u stream: lane l reads float2 (units u0,u1); 256B coalesced per warp-step
    const float2* up = reinterpret_cast<const float2*>(g_u + (size_t)n * TT * 64) + l;

    // init h0 = ones; prefetch u_0, u_1
    *reinterpret_cast<float2*>(&hb[w][0][u0]) = make_float2(1.0f, 1.0f);
    float2 uc = __ldg(up);
    float2 un = __ldg(up + 32);
    __syncwarp();

    float h0 = 1.0f, h1 = 1.0f;

    for (int t = 0; t < TT; t++) {
        const int cur = t & 1;

        // distance-2 u prefetch (DRAM latency < 2 step-walls)
        const float2 u2 = (t + 2 < TT) ? __ldg(up + (t + 2) * 32)
                                       : make_float2(0.0f, 0.0f);

        const ulonglong2* vp = reinterpret_cast<const ulonglong2*>(&hb[w][cur][0]);

        // 2 chains (one per unit); u_t seeds the lo halves; spacing 4cy per chain
        float2 s0 = make_float2(uc.x, 0.0f);
        float2 s1 = make_float2(uc.y, 0.0f);
        ull a0 = *reinterpret_cast<ull*>(&s0);
        ull a1 = *reinterpret_cast<ull*>(&s1);

        #pragma unroll
        for (int g = 0; g < 16; g++) {
            const ulonglong2 v = vp[g];
            asm("fma.rn.f32x2 %0, %1, %2, %0;" : "+l"(a0) : "l"(v.x), "l"(W0[2 * g]));
            asm("fma.rn.f32x2 %0, %1, %2, %0;" : "+l"(a1) : "l"(v.x), "l"(W1[2 * g]));
            asm("fma.rn.f32x2 %0, %1, %2, %0;" : "+l"(a0) : "l"(v.y), "l"(W0[2 * g + 1]));
            asm("fma.rn.f32x2 %0, %1, %2, %0;" : "+l"(a1) : "l"(v.y), "l"(W1[2 * g + 1]));
        }

        float r0x, r0y, r1x, r1y;
        asm("mov.b64 {%0, %1}, %2;" : "=f"(r0x), "=f"(r0y) : "l"(a0));
        asm("mov.b64 {%0, %1}, %2;" : "=f"(r1x), "=f"(r1y) : "l"(a1));

        h0 = tanh_acc(r0x + r0y);
        h1 = tanh_acc(r1x + r1y);

        // publish into the other parity of this warp's private buffer
        *reinterpret_cast<float2*>(&hb[w][cur ^ 1][u0]) = make_float2(h0, h1);
        __syncwarp();

        uc = un; un = u2;
    }

    // ---- output head: sigmoid(h . fc_w + fc_b), pure warp reduction ----
    float p = h0 * fc_w[u0] + h1 * fc_w[u1];
    #pragma unroll
    for (int o = 16; o; o >>= 1) p += __shfl_xor_sync(0xffffffffu, p, o);
    if (l == 0)
        out[n] = __fdividef(1.0f, 1.0f + __expf(-(p + fc_b[0])));
}

extern "C" void kernel_launch(void* const* d_in, const int* in_sizes, int n_in,
                              void* d_out, int out_size) {
    const float* x    = (const float*)d_in[0];
    const float* W_ih = (const float*)d_in[1];
    const float* W_hh = (const float*)d_in[2];
    const float* b_ih = (const float*)d_in[3];
    const float* b_hh = (const float*)d_in[4];
    const float* fc_w = (const float*)d_in[5];
    const float* fc_b = (const float*)d_in[6];
    float* out = (float*)d_out;

    precompute_u_kernel<<<NN, 128>>>(x, W_ih, b_ih, b_hh);
    rnn_rec_kernel<<<NN / 2, 64>>>(W_hh, fc_w, fc_b, out);
}